// round 1
// baseline (speedup 1.0000x reference)
#include <cuda_runtime.h>
#include <math.h>

#define L_   2
#define B_   32
#define S_   512
#define D_   512
#define H_   8
#define DH_  64
#define DFF_ 2048
#define NTOK (B_*S_)
#define KIDX 5

// ---------------- scratch (device globals; no allocation allowed) ----------------
__device__ float g_x[NTOK*D_];
__device__ float g_y[NTOK*D_];
__device__ float g_qk[NTOK*D_];
__device__ float g_v[NTOK*D_];
__device__ float g_attn[NTOK*D_];
__device__ float g_proj[NTOK*D_];
__device__ float g_ff[NTOK*DFF_];
__device__ float g_scores[B_*H_*S_*S_];   // 268 MB

// ---------------- elementwise: x = emb + pos (pos broadcast over batch) ----------
__global__ void add_pos_kernel(const float4* __restrict__ emb,
                               const float4* __restrict__ pos,
                               float4* __restrict__ out, int n4, int posmask) {
    int i = blockIdx.x * blockDim.x + threadIdx.x;
    if (i < n4) {
        float4 a = emb[i];
        float4 p = pos[i & posmask];
        out[i] = make_float4(a.x + p.x, a.y + p.y, a.z + p.z, a.w + p.w);
    }
}

// ---------------- SGEMM: C[M,N] = A[M,K] @ B[K,N] + bias (optional relu) ---------
// 128x128 tile, BK=8, 256 threads, 8x8 per thread. Requires M%128==0, N%128==0, K%8==0.
__global__ __launch_bounds__(256) void sgemm_bias_kernel(
    const float* __restrict__ A, const float* __restrict__ B,
    const float* __restrict__ bias, float* __restrict__ C,
    int M, int N, int K, int relu)
{
    __shared__ float As[8][128];
    __shared__ float Bs[8][128];
    const int tid = threadIdx.x;
    const int bx = blockIdx.x, by = blockIdx.y;

    const int arow = tid >> 1;          // 0..127
    const int acol = (tid & 1) << 2;    // 0 or 4
    const int brow = tid >> 5;          // 0..7
    const int bcol = (tid & 31) << 2;   // 0..124

    const float* Ap = A + (size_t)(by * 128 + arow) * K + acol;
    const float* Bp = B + (size_t)brow * N + bx * 128 + bcol;

    const int tx = (tid & 15) << 3;     // 0..120
    const int ty = (tid >> 4) << 3;     // 0..120

    float acc[8][8];
#pragma unroll
    for (int i = 0; i < 8; i++)
#pragma unroll
        for (int j = 0; j < 8; j++) acc[i][j] = 0.f;

    for (int k0 = 0; k0 < K; k0 += 8) {
        float4 a = *(const float4*)(Ap + k0);
        float4 bv = *(const float4*)(Bp + (size_t)k0 * N);
        As[acol + 0][arow] = a.x;
        As[acol + 1][arow] = a.y;
        As[acol + 2][arow] = a.z;
        As[acol + 3][arow] = a.w;
        *(float4*)&Bs[brow][bcol] = bv;
        __syncthreads();
#pragma unroll
        for (int kk = 0; kk < 8; kk++) {
            float ar[8], br[8];
#pragma unroll
            for (int i = 0; i < 8; i++) ar[i] = As[kk][ty + i];
#pragma unroll
            for (int j = 0; j < 8; j++) br[j] = Bs[kk][tx + j];
#pragma unroll
            for (int i = 0; i < 8; i++)
#pragma unroll
                for (int j = 0; j < 8; j++)
                    acc[i][j] = fmaf(ar[i], br[j], acc[i][j]);
        }
        __syncthreads();
    }

#pragma unroll
    for (int i = 0; i < 8; i++) {
        size_t row = (size_t)(by * 128 + ty + i);
        float* Crow = C + row * N + bx * 128 + tx;
#pragma unroll
        for (int j = 0; j < 8; j++) {
            float v = acc[i][j] + bias[bx * 128 + tx + j];
            if (relu) v = fmaxf(v, 0.f);
            Crow[j] = v;
        }
    }
}

// ---------------- batched QK^T (q==k buffer), lower-triangular blocks only -------
// grid (S/64, S/64, B*H), block 256; scores[bh][i][j] = dot(q_i, q_j)/8
__global__ __launch_bounds__(256) void score_gemm_kernel(
    const float* __restrict__ qk, float* __restrict__ scores)
{
    const int bj = blockIdx.x, bi = blockIdx.y, bh = blockIdx.z;
    if (bj > bi) return;                          // strictly-causal: upper blocks never read
    const int b = bh >> 3, h = bh & 7;

    __shared__ float Qs[64][65];
    __shared__ float Ks[64][65];
    const int tid = threadIdx.x;
    const int r = tid >> 2;                        // 0..63
    const int c0 = (tid & 3) << 4;                 // 0,16,32,48

    const float* base = qk + (size_t)b * S_ * D_ + h * DH_;
    const float* qrow = base + (size_t)(bi * 64 + r) * D_;
    const float* krow = base + (size_t)(bj * 64 + r) * D_;
#pragma unroll
    for (int u = 0; u < 16; u += 4) {
        float4 qa = *(const float4*)(qrow + c0 + u);
        Qs[r][c0 + u] = qa.x; Qs[r][c0 + u + 1] = qa.y;
        Qs[r][c0 + u + 2] = qa.z; Qs[r][c0 + u + 3] = qa.w;
        float4 ka = *(const float4*)(krow + c0 + u);
        Ks[r][c0 + u] = ka.x; Ks[r][c0 + u + 1] = ka.y;
        Ks[r][c0 + u + 2] = ka.z; Ks[r][c0 + u + 3] = ka.w;
    }
    __syncthreads();

    const int ti = (tid >> 4) << 2;                // 0..60
    const int tj = (tid & 15) << 2;                // 0..60
    float acc[4][4];
#pragma unroll
    for (int i = 0; i < 4; i++)
#pragma unroll
        for (int j = 0; j < 4; j++) acc[i][j] = 0.f;

#pragma unroll 8
    for (int d = 0; d < 64; d++) {
        float ar[4], br[4];
#pragma unroll
        for (int i = 0; i < 4; i++) ar[i] = Qs[ti + i][d];
#pragma unroll
        for (int j = 0; j < 4; j++) br[j] = Ks[tj + j][d];
#pragma unroll
        for (int i = 0; i < 4; i++)
#pragma unroll
            for (int j = 0; j < 4; j++)
                acc[i][j] = fmaf(ar[i], br[j], acc[i][j]);
    }

#pragma unroll
    for (int i = 0; i < 4; i++) {
        int gi = bi * 64 + ti + i;
        float* srow = scores + ((size_t)bh * S_ + gi) * S_;
#pragma unroll
        for (int j = 0; j < 4; j++)
            srow[bj * 64 + tj + j] = acc[i][j] * 0.125f;   // / sqrt(64)
    }
}

// ---------------- softmax + top-5 prob-space sparsification + PV -----------------
// grid (S, H, B), block 128; one block per query row.
__global__ __launch_bounds__(128) void attn_topk_kernel(
    const float* __restrict__ scores, const float* __restrict__ v,
    float* __restrict__ out)
{
    const int i = blockIdx.x, h = blockIdx.y, b = blockIdx.z;
    const int tid = threadIdx.x;
    float* orow = out + ((size_t)(b * S_ + i)) * D_ + h * DH_;

    if (i == 0) {                                  // zero_pad: first query row = 0
        if (tid < DH_) orow[tid] = 0.f;
        return;
    }

    __shared__ float p[S_];
    __shared__ float rv[128];
    __shared__ int   ri[128];
    __shared__ int   sel[KIDX];
    __shared__ float selv[KIDX];
    __shared__ int   cnt;
    __shared__ int   kidx[64];
    __shared__ float ke[64];
    __shared__ float zinv_s;

    const float* srow = scores + (((size_t)(b * H_ + h)) * S_ + i) * S_;

    // --- max over valid keys j < i ---
    float lmx = -1e30f;
    for (int j = tid; j < i; j += 128) { float s = srow[j]; p[j] = s; lmx = fmaxf(lmx, s); }
    rv[tid] = lmx; __syncthreads();
    for (int o = 64; o; o >>= 1) { if (tid < o) rv[tid] = fmaxf(rv[tid], rv[tid + o]); __syncthreads(); }
    const float mx = rv[0];
    __syncthreads();

    // --- exp + sum ---
    float lsum = 0.f;
    for (int j = tid; j < i; j += 128) { float e = __expf(p[j] - mx); p[j] = e; lsum += e; }
    rv[tid] = lsum; __syncthreads();
    for (int o = 64; o; o >>= 1) { if (tid < o) rv[tid] += rv[tid + o]; __syncthreads(); }
    const float inv = 1.f / rv[0];
    __syncthreads();
    for (int j = tid; j < i; j += 128) p[j] *= inv;   // p[j] = softmax prob
    __syncthreads();

    if (i <= KIDX) {                               // dense rows 1..5
        if (tid < DH_) {
            float acc = 0.f;
            for (int j = 0; j < i; j++)
                acc += p[j] * v[((size_t)(b * S_ + j)) * D_ + h * DH_ + tid];
            orow[tid] = acc;
        }
        return;
    }

    // --- top-5 extraction (argmax with marking; replicates top_k incl. ties) ---
    for (int pass = 0; pass < KIDX; pass++) {
        float bvv = -1e30f; int bii = -1;
        for (int j = tid; j < i; j += 128) {
            bool skip = false;
            for (int q = 0; q < pass; q++) if (sel[q] == j) skip = true;
            float pv = p[j];
            if (!skip && pv > bvv) { bvv = pv; bii = j; }
        }
        rv[tid] = bvv; ri[tid] = bii; __syncthreads();
        for (int o = 64; o; o >>= 1) {
            if (tid < o && rv[tid + o] > rv[tid]) { rv[tid] = rv[tid + o]; ri[tid] = ri[tid + o]; }
            __syncthreads();
        }
        if (tid == 0) { sel[pass] = ri[0]; selv[pass] = rv[0]; }
        __syncthreads();
    }
    const float thresh = selv[KIDX - 1];
    const float mxp = selv[0];

    // --- collect kept entries (p >= thresh, matching "scores - thresh >= 0") ---
    if (tid == 0) cnt = 0;
    __syncthreads();
    for (int j = tid; j < i; j += 128)
        if (p[j] >= thresh) { int pos = atomicAdd(&cnt, 1); if (pos < 64) kidx[pos] = j; }
    __syncthreads();
    const int c = min(cnt, 64);

    // --- softmax OF the kept probabilities (JAX does softmax(probs)) ---
    if (tid < c) ke[tid] = __expf(p[kidx[tid]] - mxp);
    __syncthreads();
    if (tid == 0) { float z = 0.f; for (int e = 0; e < c; e++) z += ke[e]; zinv_s = 1.f / z; }
    __syncthreads();

    if (tid < DH_) {
        float acc = 0.f;
        for (int e = 0; e < c; e++)
            acc += ke[e] * zinv_s * v[((size_t)(b * S_ + kidx[e])) * D_ + h * DH_ + tid];
        orow[tid] = acc;
    }
}

// ---------------- residual + LayerNorm -------------------------------------------
// dst[row] = LN(xin[row] + res[row]) * g + b ; grid NTOK, block 128
__global__ __launch_bounds__(128) void add_ln_kernel(
    float* __restrict__ dst, const float* __restrict__ xin,
    const float* __restrict__ res, const float* __restrict__ g,
    const float* __restrict__ bb)
{
    const int row = blockIdx.x, tid = threadIdx.x;
    __shared__ float sh[D_];
    __shared__ float red[128];
    const size_t off = (size_t)row * D_;

    float ls = 0.f;
    for (int k = tid; k < D_; k += 128) { float v = xin[off + k] + res[off + k]; sh[k] = v; ls += v; }
    red[tid] = ls; __syncthreads();
    for (int o = 64; o; o >>= 1) { if (tid < o) red[tid] += red[tid + o]; __syncthreads(); }
    const float mean = red[0] * (1.f / D_);
    __syncthreads();

    float lq = 0.f;
    for (int k = tid; k < D_; k += 128) { float d = sh[k] - mean; lq += d * d; }
    red[tid] = lq; __syncthreads();
    for (int o = 64; o; o >>= 1) { if (tid < o) red[tid] += red[tid + o]; __syncthreads(); }
    const float rstd = rsqrtf(red[0] * (1.f / D_) + 1e-5f);
    __syncthreads();

    for (int k = tid; k < D_; k += 128)
        dst[off + k] = (sh[k] - mean) * rstd * g[k] + bb[k];
}

// ---------------- host orchestration ---------------------------------------------
extern "C" void kernel_launch(void* const* d_in, const int* in_sizes, int n_in,
                              void* d_out, int out_size)
{
    const float* qe   = (const float*)d_in[0];
    const float* ie   = (const float*)d_in[1];
    const float* pos  = (const float*)d_in[2];
    const float* Wk   = (const float*)d_in[3];
    const float* bk   = (const float*)d_in[4];
    const float* Wv   = (const float*)d_in[5];
    const float* bv   = (const float*)d_in[6];
    const float* Wo   = (const float*)d_in[7];
    const float* bo   = (const float*)d_in[8];
    const float* ln1g = (const float*)d_in[9];
    const float* ln1b = (const float*)d_in[10];
    const float* W1   = (const float*)d_in[11];
    const float* b1   = (const float*)d_in[12];
    const float* W2   = (const float*)d_in[13];
    const float* b2   = (const float*)d_in[14];
    const float* ln2g = (const float*)d_in[15];
    const float* ln2b = (const float*)d_in[16];
    float* out = (float*)d_out;

    float *x, *y, *qkp, *vp, *attn, *proj, *ff, *sc;
    cudaGetSymbolAddress((void**)&x,    g_x);
    cudaGetSymbolAddress((void**)&y,    g_y);
    cudaGetSymbolAddress((void**)&qkp,  g_qk);
    cudaGetSymbolAddress((void**)&vp,   g_v);
    cudaGetSymbolAddress((void**)&attn, g_attn);
    cudaGetSymbolAddress((void**)&proj, g_proj);
    cudaGetSymbolAddress((void**)&ff,   g_ff);
    cudaGetSymbolAddress((void**)&sc,   g_scores);

    const int n4 = NTOK * D_ / 4;
    const int posmask = S_ * D_ / 4 - 1;   // pos repeats every S*D floats (power of 2)
    add_pos_kernel<<<(n4 + 255) / 256, 256>>>((const float4*)qe, (const float4*)pos, (float4*)x, n4, posmask);
    add_pos_kernel<<<(n4 + 255) / 256, 256>>>((const float4*)ie, (const float4*)pos, (float4*)y, n4, posmask);

    for (int l = 0; l < L_; l++) {
        const float* Wkl = Wk + (size_t)l * D_ * D_;
        const float* Wvl = Wv + (size_t)l * D_ * D_;
        const float* Wol = Wo + (size_t)l * D_ * D_;
        const float* W1l = W1 + (size_t)l * D_ * DFF_;
        const float* W2l = W2 + (size_t)l * DFF_ * D_;

        // q == k (kq_same): single projection
        sgemm_bias_kernel<<<dim3(D_ / 128, NTOK / 128), 256>>>(x, Wkl, bk + l * D_, qkp, NTOK, D_, D_, 0);
        sgemm_bias_kernel<<<dim3(D_ / 128, NTOK / 128), 256>>>(y, Wvl, bv + l * D_, vp,  NTOK, D_, D_, 0);

        score_gemm_kernel<<<dim3(S_ / 64, S_ / 64, B_ * H_), 256>>>(qkp, sc);
        attn_topk_kernel<<<dim3(S_, H_, B_), 128>>>(sc, vp, attn);

        sgemm_bias_kernel<<<dim3(D_ / 128, NTOK / 128), 256>>>(attn, Wol, bo + l * D_, proj, NTOK, D_, D_, 0);
        add_ln_kernel<<<NTOK, 128>>>(x, x, proj, ln1g + l * D_, ln1b + l * D_);

        sgemm_bias_kernel<<<dim3(DFF_ / 128, NTOK / 128), 256>>>(x,  W1l, b1 + l * DFF_, ff,   NTOK, DFF_, D_,   1);
        sgemm_bias_kernel<<<dim3(D_ / 128,  NTOK / 128), 256>>>(ff, W2l, b2 + l * D_,   proj, NTOK, D_,   DFF_, 0);

        float* dst = (l == L_ - 1) ? out : x;
        add_ln_kernel<<<NTOK, 128>>>(dst, x, proj, ln2g + l * D_, ln2b + l * D_);
    }
}